// round 5
// baseline (speedup 1.0000x reference)
#include <cuda_runtime.h>

#define NNODES 100000
#define NEDGES 1600000
#define DF 128
#define NCLS 40
#define TM 128
#define TLD 132   // padded tile stride (floats)
#define FTM 64
#define SCAN_T 1024
#define SCAN_CHUNK ((NNODES + SCAN_T - 1) / SCAN_T)   // 98

// Scratch (allocation-free rule: __device__ globals)
__device__ float g_pre[NNODES * DF];
__device__ float g_h1[NNODES * DF];
__device__ float g_h2[NNODES * DF];
__device__ int   g_csr[NEDGES];
__device__ int   g_deg[NNODES];
__device__ int   g_off[NNODES + 1];
__device__ int   g_cur[NNODES];

// ---- packed f32x2 helpers ---------------------------------------------------
__device__ __forceinline__ unsigned long long pack2(float x, float y) {
    unsigned long long r;
    asm("mov.b64 %0, {%1,%2};" : "=l"(r)
        : "r"(__float_as_uint(x)), "r"(__float_as_uint(y)));
    return r;
}
__device__ __forceinline__ unsigned long long packdup(float x) {
    unsigned long long r;
    asm("mov.b64 %0, {%1,%1};" : "=l"(r) : "r"(__float_as_uint(x)));
    return r;
}
#define FMA2(d, a, b, c) \
    asm("fma.rn.f32x2 %0, %1, %2, %3;" : "=l"(d) : "l"(a), "l"(b), "l"(c))

__device__ __forceinline__ bool edges_are_i64(const int* raw) {
    return (raw[1] | raw[3] | raw[5] | raw[7] |
            raw[9] | raw[11] | raw[13] | raw[15]) == 0;
}

// ---------------------------------------------------------------------------
__global__ void zero_int_kernel(int* __restrict__ p, int n) {
    int i = blockIdx.x * blockDim.x + threadIdx.x;
    if (i < n) p[i] = 0;
}

// Degree histogram by dst, reading edge_index raw (int32/int64 robust).
__global__ void hist_kernel(const int* __restrict__ raw, int* __restrict__ deg) {
    bool is64 = edges_are_i64(raw);
    int i = blockIdx.x * blockDim.x + threadIdx.x;
    if (i >= NEDGES) return;
    int d = is64 ? raw[2 * NEDGES + 2 * i] : raw[NEDGES + i];
    atomicAdd(deg + d, 1);
}

// Single-block exclusive scan of degrees -> offsets (+ cursor copy).
__global__ __launch_bounds__(SCAN_T, 1)
void scan_kernel(const int* __restrict__ deg, int* __restrict__ off,
                 int* __restrict__ cur) {
    __shared__ int s[SCAN_T];
    int t = threadIdx.x;
    int base = t * SCAN_CHUNK;
    int sum = 0;
    for (int i = 0; i < SCAN_CHUNK; i++) {
        int idx = base + i;
        if (idx < NNODES) sum += deg[idx];
    }
    s[t] = sum;
    __syncthreads();
    for (int ofs = 1; ofs < SCAN_T; ofs <<= 1) {
        int v = (t >= ofs) ? s[t - ofs] : 0;
        __syncthreads();
        s[t] += v;
        __syncthreads();
    }
    int run = (t == 0) ? 0 : s[t - 1];
    for (int i = 0; i < SCAN_CHUNK; i++) {
        int idx = base + i;
        if (idx < NNODES) {
            off[idx] = run;
            cur[idx] = run;
            run += deg[idx];
        }
    }
    if (t == 0) off[NNODES] = s[SCAN_T - 1];
}

__global__ void scatter_kernel(const int* __restrict__ raw,
                               int* __restrict__ cur,
                               int* __restrict__ csr) {
    bool is64 = edges_are_i64(raw);
    int i = blockIdx.x * blockDim.x + threadIdx.x;
    if (i >= NEDGES) return;
    int s, d;
    if (is64) { s = raw[2 * i]; d = raw[2 * NEDGES + 2 * i]; }
    else      { s = raw[i];     d = raw[NEDGES + i]; }
    int pos = atomicAdd(cur + d, 1);
    csr[pos] = s;
}

// ---------------------------------------------------------------------------
// Gather aggregation, no atomics: pre[node] = xin[node] + sum_{nbr} feat[nbr].
// Warp per node, 32 lanes x float4 = 512B row, 8 rows in flight.
__global__ void agg_kernel(const float* __restrict__ feat,
                           const float* __restrict__ xin,
                           const int* __restrict__ off,
                           const int* __restrict__ csr,
                           float* __restrict__ pre) {
    int node = (blockIdx.x * blockDim.x + threadIdx.x) >> 5;
    int lane = threadIdx.x & 31;
    if (node >= NNODES) return;
    int e0 = off[node], e1 = off[node + 1];
    float4 acc = reinterpret_cast<const float4*>(xin + (size_t)node * DF)[lane];
    int e = e0;
#pragma unroll 1
    for (; e + 8 <= e1; e += 8) {
        int n[8];
#pragma unroll
        for (int j = 0; j < 8; j++) n[j] = __ldg(csr + e + j);
        float4 v[8];
#pragma unroll
        for (int j = 0; j < 8; j++)
            v[j] = *reinterpret_cast<const float4*>(feat + (size_t)n[j] * DF + lane * 4);
#pragma unroll
        for (int j = 0; j < 8; j++) {
            acc.x += v[j].x; acc.y += v[j].y; acc.z += v[j].z; acc.w += v[j].w;
        }
    }
    for (; e < e1; e++) {
        int n0 = __ldg(csr + e);
        float4 v0 = *reinterpret_cast<const float4*>(feat + (size_t)n0 * DF + lane * 4);
        acc.x += v0.x; acc.y += v0.y; acc.z += v0.z; acc.w += v0.w;
    }
    *reinterpret_cast<float4*>(pre + (size_t)node * DF + lane * 4) = acc;
}

// ---------------------------------------------------------------------------
// Fused GIN MLP with packed f32x2 FMA, 128-row tile, 512 threads:
// out = relu( relu( pre @ wa + ba ) @ wb + bb )
// Each thread: 4 rows x 8 cols. Intermediate h written back into the tile.
__global__ __launch_bounds__(512, 1)
void mlp_kernel(const float* __restrict__ pre,
                const float* __restrict__ wa, const float* __restrict__ ba,
                const float* __restrict__ wb, const float* __restrict__ bb,
                float* __restrict__ out) {
    extern __shared__ float sm[];
    float* ws_a = sm;                 // 128*128
    float* ws_b = sm + DF * DF;       // 128*128
    float* tile = sm + 2 * DF * DF;   // TM*TLD (input, then h)

    const int t = threadIdx.x;
    const int row0 = blockIdx.x * TM;

    // Load both weight matrices (k-major: w[k*128 + n])
    {
        const float4* wa4 = reinterpret_cast<const float4*>(wa);
        const float4* wb4 = reinterpret_cast<const float4*>(wb);
        float4* wsa4 = reinterpret_cast<float4*>(ws_a);
        float4* wsb4 = reinterpret_cast<float4*>(ws_b);
#pragma unroll
        for (int i = 0; i < (DF * DF / 4) / 512; i++) {   // 8 iters each
            wsa4[t + i * 512] = wa4[t + i * 512];
            wsb4[t + i * 512] = wb4[t + i * 512];
        }
    }

    // Load input tile (128 rows x 128 cols)
    {
        int c4 = t & 31;
        int rr = t >> 5;   // 0..15
#pragma unroll
        for (int i = 0; i < TM / 16; i++) {
            int r = rr + i * 16;
            int gr = row0 + r;
            float4 v = make_float4(0.f, 0.f, 0.f, 0.f);
            if (gr < NNODES)
                v = reinterpret_cast<const float4*>(pre + (size_t)gr * DF)[c4];
            *reinterpret_cast<float4*>(&tile[r * TLD + c4 * 4]) = v;
        }
    }
    __syncthreads();

    const int tx = t & 15;          // 16 column groups of 8
    const int ty = t >> 4;          // 32 row groups of 4
    const int col = tx * 8;
    const int rbase = ty * 4;

    unsigned long long acc[4][4];   // 4 rows x 4 packed pairs

    // ---- GEMM 1: h = relu(tile @ wa + ba) ----
    {
        float4 bv0 = *reinterpret_cast<const float4*>(ba + col);
        float4 bv1 = *reinterpret_cast<const float4*>(ba + col + 4);
        unsigned long long bp[4] = {pack2(bv0.x, bv0.y), pack2(bv0.z, bv0.w),
                                    pack2(bv1.x, bv1.y), pack2(bv1.z, bv1.w)};
#pragma unroll
        for (int i = 0; i < 4; i++)
#pragma unroll
            for (int j = 0; j < 4; j++) acc[i][j] = bp[j];
    }
#pragma unroll 2
    for (int k4 = 0; k4 < DF / 4; k4++) {
        const int k = k4 * 4;
        float a_[4][4];
#pragma unroll
        for (int i = 0; i < 4; i++) {
            float4 f = *reinterpret_cast<const float4*>(&tile[(rbase + i) * TLD + k]);
            a_[i][0] = f.x; a_[i][1] = f.y; a_[i][2] = f.z; a_[i][3] = f.w;
        }
#pragma unroll
        for (int kk = 0; kk < 4; kk++) {
            ulonglong2 q0 = *reinterpret_cast<const ulonglong2*>(&ws_a[(k + kk) * DF + col]);
            ulonglong2 q1 = *reinterpret_cast<const ulonglong2*>(&ws_a[(k + kk) * DF + col + 4]);
#pragma unroll
            for (int i = 0; i < 4; i++) {
                unsigned long long ap = packdup(a_[i][kk]);
                FMA2(acc[i][0], ap, q0.x, acc[i][0]);
                FMA2(acc[i][1], ap, q0.y, acc[i][1]);
                FMA2(acc[i][2], ap, q1.x, acc[i][2]);
                FMA2(acc[i][3], ap, q1.y, acc[i][3]);
            }
        }
    }
    __syncthreads();   // all reads of tile complete
#pragma unroll
    for (int i = 0; i < 4; i++) {
        float v[8];
#pragma unroll
        for (int j = 0; j < 4; j++) {
            uint2 u = *reinterpret_cast<uint2*>(&acc[i][j]);
            v[2 * j]     = fmaxf(__uint_as_float(u.x), 0.f);
            v[2 * j + 1] = fmaxf(__uint_as_float(u.y), 0.f);
        }
        *reinterpret_cast<float4*>(&tile[(rbase + i) * TLD + col]) =
            make_float4(v[0], v[1], v[2], v[3]);
        *reinterpret_cast<float4*>(&tile[(rbase + i) * TLD + col + 4]) =
            make_float4(v[4], v[5], v[6], v[7]);
    }
    __syncthreads();

    // ---- GEMM 2: out = relu(h @ wb + bb) ----
    {
        float4 bv0 = *reinterpret_cast<const float4*>(bb + col);
        float4 bv1 = *reinterpret_cast<const float4*>(bb + col + 4);
        unsigned long long bp[4] = {pack2(bv0.x, bv0.y), pack2(bv0.z, bv0.w),
                                    pack2(bv1.x, bv1.y), pack2(bv1.z, bv1.w)};
#pragma unroll
        for (int i = 0; i < 4; i++)
#pragma unroll
            for (int j = 0; j < 4; j++) acc[i][j] = bp[j];
    }
#pragma unroll 2
    for (int k4 = 0; k4 < DF / 4; k4++) {
        const int k = k4 * 4;
        float a_[4][4];
#pragma unroll
        for (int i = 0; i < 4; i++) {
            float4 f = *reinterpret_cast<const float4*>(&tile[(rbase + i) * TLD + k]);
            a_[i][0] = f.x; a_[i][1] = f.y; a_[i][2] = f.z; a_[i][3] = f.w;
        }
#pragma unroll
        for (int kk = 0; kk < 4; kk++) {
            ulonglong2 q0 = *reinterpret_cast<const ulonglong2*>(&ws_b[(k + kk) * DF + col]);
            ulonglong2 q1 = *reinterpret_cast<const ulonglong2*>(&ws_b[(k + kk) * DF + col + 4]);
#pragma unroll
            for (int i = 0; i < 4; i++) {
                unsigned long long ap = packdup(a_[i][kk]);
                FMA2(acc[i][0], ap, q0.x, acc[i][0]);
                FMA2(acc[i][1], ap, q0.y, acc[i][1]);
                FMA2(acc[i][2], ap, q1.x, acc[i][2]);
                FMA2(acc[i][3], ap, q1.y, acc[i][3]);
            }
        }
    }
#pragma unroll
    for (int i = 0; i < 4; i++) {
        int gr = row0 + rbase + i;
        if (gr >= NNODES) continue;
        float v[8];
#pragma unroll
        for (int j = 0; j < 4; j++) {
            uint2 u = *reinterpret_cast<uint2*>(&acc[i][j]);
            v[2 * j]     = fmaxf(__uint_as_float(u.x), 0.f);
            v[2 * j + 1] = fmaxf(__uint_as_float(u.y), 0.f);
        }
        *reinterpret_cast<float4*>(out + (size_t)gr * DF + col) =
            make_float4(v[0], v[1], v[2], v[3]);
        *reinterpret_cast<float4*>(out + (size_t)gr * DF + col + 4) =
            make_float4(v[4], v[5], v[6], v[7]);
    }
}

// ---------------------------------------------------------------------------
// Final FC (128 -> 40) + log_softmax, fused. 320 threads, 64 rows per block.
__global__ __launch_bounds__(320, 1)
void fc_softmax_kernel(const float* __restrict__ h, const float* __restrict__ wfc,
                       const float* __restrict__ bfc, float* __restrict__ out) {
    extern __shared__ float sm[];
    float* wsm   = sm;                         // DF*NCLS = 5120
    float* tile  = sm + DF * NCLS;             // FTM*DF  = 8192
    float* lg    = tile + FTM * DF;            // FTM*NCLS = 2560
    float* rstat = lg + FTM * NCLS;            // 2*FTM
    __shared__ float bsm[NCLS];

    const int t = threadIdx.x;
    const int row0 = blockIdx.x * FTM;

    for (int i = t; i < DF * NCLS; i += 320) wsm[i] = wfc[i];
    if (t < NCLS) bsm[t] = bfc[t];
    for (int i = t; i < FTM * DF / 4; i += 320) {
        int r = i >> 5;
        int c4 = i & 31;
        int gr = row0 + r;
        float4 v = (gr < NNODES)
                       ? reinterpret_cast<const float4*>(h + (size_t)gr * DF)[c4]
                       : make_float4(0.f, 0.f, 0.f, 0.f);
        reinterpret_cast<float4*>(tile)[i] = v;
    }
    __syncthreads();

    const int r = t / 5;
    const int cg = t % 5;
    const int cb = cg * 8;
    float acc[8];
#pragma unroll
    for (int j = 0; j < 8; j++) acc[j] = bsm[cb + j];
#pragma unroll 4
    for (int k = 0; k < DF; k++) {
        float a = tile[r * DF + k];
        float4 w0 = *reinterpret_cast<const float4*>(&wsm[k * NCLS + cb]);
        float4 w1 = *reinterpret_cast<const float4*>(&wsm[k * NCLS + cb + 4]);
        acc[0] += a * w0.x; acc[1] += a * w0.y; acc[2] += a * w0.z; acc[3] += a * w0.w;
        acc[4] += a * w1.x; acc[5] += a * w1.y; acc[6] += a * w1.z; acc[7] += a * w1.w;
    }
#pragma unroll
    for (int j = 0; j < 8; j++) lg[r * NCLS + cb + j] = acc[j];
    __syncthreads();

    if (t < FTM) {
        float m = -1e30f;
#pragma unroll
        for (int c = 0; c < NCLS; c++) m = fmaxf(m, lg[t * NCLS + c]);
        float s = 0.f;
#pragma unroll
        for (int c = 0; c < NCLS; c++) s += expf(lg[t * NCLS + c] - m);
        rstat[t] = m;
        rstat[FTM + t] = logf(s);
    }
    __syncthreads();

    int gr = row0 + r;
    if (gr < NNODES) {
        float m = rstat[r], ls = rstat[FTM + r];
#pragma unroll
        for (int j = 0; j < 8; j++)
            out[(size_t)gr * NCLS + cb + j] = lg[r * NCLS + cb + j] - m - ls;
    }
}

// ---------------------------------------------------------------------------
extern "C" void kernel_launch(void* const* d_in, const int* in_sizes, int n_in,
                              void* d_out, int out_size) {
    const float* x        = (const float*)d_in[0];
    const int*   ei_raw   = (const int*)d_in[1];
    const float* w1a      = (const float*)d_in[2];
    const float* b1a      = (const float*)d_in[3];
    const float* w1b      = (const float*)d_in[4];
    const float* b1b      = (const float*)d_in[5];
    const float* w2a      = (const float*)d_in[6];
    const float* b2a      = (const float*)d_in[7];
    const float* w2b      = (const float*)d_in[8];
    const float* b2b      = (const float*)d_in[9];
    const float* wfc      = (const float*)d_in[10];
    const float* bfc      = (const float*)d_in[11];
    float* out            = (float*)d_out;

    float *pre, *h1, *h2;
    int *csr, *deg, *off, *cur;
    cudaGetSymbolAddress((void**)&pre, g_pre);
    cudaGetSymbolAddress((void**)&h1, g_h1);
    cudaGetSymbolAddress((void**)&h2, g_h2);
    cudaGetSymbolAddress((void**)&csr, g_csr);
    cudaGetSymbolAddress((void**)&deg, g_deg);
    cudaGetSymbolAddress((void**)&off, g_off);
    cudaGetSymbolAddress((void**)&cur, g_cur);

    const size_t mlp_smem = (size_t)(2 * DF * DF + TM * TLD) * sizeof(float);
    const size_t fc_smem  = (size_t)(DF * NCLS + FTM * DF + FTM * NCLS + 2 * FTM) * sizeof(float);
    cudaFuncSetAttribute(mlp_kernel, cudaFuncAttributeMaxDynamicSharedMemorySize, (int)mlp_smem);
    cudaFuncSetAttribute(fc_softmax_kernel, cudaFuncAttributeMaxDynamicSharedMemorySize, (int)fc_smem);

    const int egrid = (NEDGES + 255) / 256;
    const int ngrid = (NNODES + 255) / 256;
    const int agrid = (int)(((long long)NNODES * 32 + 255) / 256);
    const int mgrid = (NNODES + TM - 1) / TM;
    const int fgrid = (NNODES + FTM - 1) / FTM;

    // --- CSR build ---
    zero_int_kernel<<<ngrid, 256>>>(deg, NNODES);
    hist_kernel<<<egrid, 256>>>(ei_raw, deg);
    scan_kernel<<<1, SCAN_T>>>(deg, off, cur);
    scatter_kernel<<<egrid, 256>>>(ei_raw, cur, csr);

    // Layer 1
    agg_kernel<<<agrid, 256>>>(x, x, off, csr, pre);
    mlp_kernel<<<mgrid, 512, mlp_smem>>>(pre, w1a, b1a, w1b, b1b, h1);
    // Layer 2
    agg_kernel<<<agrid, 256>>>(h1, h1, off, csr, pre);
    mlp_kernel<<<mgrid, 512, mlp_smem>>>(pre, w2a, b2a, w2b, b2b, h2);
    // Head
    fc_softmax_kernel<<<fgrid, 320, fc_smem>>>(h2, wfc, bfc, out);
}

// round 6
// speedup vs baseline: 1.1654x; 1.1654x over previous
#include <cuda_runtime.h>

#define NNODES 100000
#define NEDGES 1600000
#define DF 128
#define NCLS 40
#define TM 128
#define TLD 132   // padded tile stride (floats)
#define SCAN_T 1024
#define SCAN_CHUNK ((NNODES + SCAN_T - 1) / SCAN_T)   // 98

// Scratch (allocation-free rule: __device__ globals)
__device__ float g_h1[NNODES * DF];
__device__ int   g_csr[NEDGES];
__device__ int   g_deg[NNODES];
__device__ int   g_off[NNODES + 1];
__device__ int   g_cur[NNODES];

// ---- packed f32x2 helpers ---------------------------------------------------
__device__ __forceinline__ unsigned long long pack2(float x, float y) {
    unsigned long long r;
    asm("mov.b64 %0, {%1,%2};" : "=l"(r)
        : "r"(__float_as_uint(x)), "r"(__float_as_uint(y)));
    return r;
}
__device__ __forceinline__ unsigned long long packdup(float x) {
    unsigned long long r;
    asm("mov.b64 %0, {%1,%1};" : "=l"(r) : "r"(__float_as_uint(x)));
    return r;
}
#define FMA2(d, a, b, c) \
    asm("fma.rn.f32x2 %0, %1, %2, %3;" : "=l"(d) : "l"(a), "l"(b), "l"(c))

__device__ __forceinline__ bool edges_are_i64(const int* raw) {
    return (raw[1] | raw[3] | raw[5] | raw[7] |
            raw[9] | raw[11] | raw[13] | raw[15]) == 0;
}

// ---------------------------------------------------------------------------
__global__ void zero_int_kernel(int* __restrict__ p, int n) {
    int i = blockIdx.x * blockDim.x + threadIdx.x;
    if (i < n) p[i] = 0;
}

__global__ void hist_kernel(const int* __restrict__ raw, int* __restrict__ deg) {
    bool is64 = edges_are_i64(raw);
    int i = blockIdx.x * blockDim.x + threadIdx.x;
    if (i >= NEDGES) return;
    int d = is64 ? raw[2 * NEDGES + 2 * i] : raw[NEDGES + i];
    atomicAdd(deg + d, 1);
}

__global__ __launch_bounds__(SCAN_T, 1)
void scan_kernel(const int* __restrict__ deg, int* __restrict__ off,
                 int* __restrict__ cur) {
    __shared__ int s[SCAN_T];
    int t = threadIdx.x;
    int base = t * SCAN_CHUNK;
    int sum = 0;
    for (int i = 0; i < SCAN_CHUNK; i++) {
        int idx = base + i;
        if (idx < NNODES) sum += deg[idx];
    }
    s[t] = sum;
    __syncthreads();
    for (int ofs = 1; ofs < SCAN_T; ofs <<= 1) {
        int v = (t >= ofs) ? s[t - ofs] : 0;
        __syncthreads();
        s[t] += v;
        __syncthreads();
    }
    int run = (t == 0) ? 0 : s[t - 1];
    for (int i = 0; i < SCAN_CHUNK; i++) {
        int idx = base + i;
        if (idx < NNODES) {
            off[idx] = run;
            cur[idx] = run;
            run += deg[idx];
        }
    }
    if (t == 0) off[NNODES] = s[SCAN_T - 1];
}

__global__ void scatter_kernel(const int* __restrict__ raw,
                               int* __restrict__ cur,
                               int* __restrict__ csr) {
    bool is64 = edges_are_i64(raw);
    int i = blockIdx.x * blockDim.x + threadIdx.x;
    if (i >= NEDGES) return;
    int s, d;
    if (is64) { s = raw[2 * i]; d = raw[2 * NEDGES + 2 * i]; }
    else      { s = raw[i];     d = raw[NEDGES + i]; }
    int pos = atomicAdd(cur + d, 1);
    csr[pos] = s;
}

// ---------------------------------------------------------------------------
// Fused GIN layer: gather + MLP (+ optional FC/log_softmax epilogue).
//   tile[r] = feat[gr] + sum_{nbr in csr[off[gr]:off[gr+1]]} feat[nbr]
//   h  = relu(tile @ wa + ba); y = relu(h @ wb + bb)
//   if wfc: out[gr] = log_softmax(y @ wfc + bfc)  else out[gr] = y
// 256 threads, 128-row tile, packed f32x2 FMA (8 rows x 8 cols per thread).
__global__ __launch_bounds__(256, 1)
void gin_layer_kernel(const float* __restrict__ feat,
                      const int* __restrict__ off,
                      const int* __restrict__ csr,
                      const float* __restrict__ wa, const float* __restrict__ ba,
                      const float* __restrict__ wb, const float* __restrict__ bb,
                      const float* __restrict__ wfc, const float* __restrict__ bfc,
                      float* __restrict__ out) {
    extern __shared__ float sm[];
    float* ws_a = sm;                       // 16384
    float* ws_b = sm + DF * DF;             // 16384
    float* tile = sm + 2 * DF * DF;         // TM*TLD = 16896
    float* wsf  = tile + TM * TLD;          // 5120 (wfc) — only used when fc
    float* bsf  = wsf + DF * NCLS;          // 40

    const int t = threadIdx.x;
    const int lane = t & 31;
    const int w = t >> 5;                   // warp 0..7
    const int row0 = blockIdx.x * TM;
    const bool do_fc = (wfc != nullptr);

    // Load weight matrices (k-major: w[k*128 + n])
    {
        const float4* wa4 = reinterpret_cast<const float4*>(wa);
        const float4* wb4 = reinterpret_cast<const float4*>(wb);
        float4* wsa4 = reinterpret_cast<float4*>(ws_a);
        float4* wsb4 = reinterpret_cast<float4*>(ws_b);
#pragma unroll
        for (int i = 0; i < (DF * DF / 4) / 256; i++) {
            wsa4[t + i * 256] = wa4[t + i * 256];
            wsb4[t + i * 256] = wb4[t + i * 256];
        }
        if (do_fc) {
            for (int i = t; i < DF * NCLS; i += 256) wsf[i] = wfc[i];
            if (t < NCLS) bsf[t] = bfc[t];
        }
    }

    // Gather: warp per row, 16 rows per warp (strided by 8).
#pragma unroll 1
    for (int i = 0; i < TM / 8; i++) {
        int r = i * 8 + w;
        int gr = row0 + r;
        float4 acc = make_float4(0.f, 0.f, 0.f, 0.f);
        if (gr < NNODES) {
            acc = *reinterpret_cast<const float4*>(feat + (size_t)gr * DF + lane * 4);
            int e = off[gr], e1 = off[gr + 1];
#pragma unroll 1
            for (; e + 8 <= e1; e += 8) {
                int n[8];
#pragma unroll
                for (int j = 0; j < 8; j++) n[j] = __ldg(csr + e + j);
                float4 v[8];
#pragma unroll
                for (int j = 0; j < 8; j++)
                    v[j] = *reinterpret_cast<const float4*>(feat + (size_t)n[j] * DF + lane * 4);
#pragma unroll
                for (int j = 0; j < 8; j++) {
                    acc.x += v[j].x; acc.y += v[j].y; acc.z += v[j].z; acc.w += v[j].w;
                }
            }
            for (; e < e1; e++) {
                int n0 = __ldg(csr + e);
                float4 v0 = *reinterpret_cast<const float4*>(feat + (size_t)n0 * DF + lane * 4);
                acc.x += v0.x; acc.y += v0.y; acc.z += v0.z; acc.w += v0.w;
            }
        }
        *reinterpret_cast<float4*>(&tile[r * TLD + lane * 4]) = acc;
    }
    __syncthreads();

    const int tx = t & 15;          // 16 column groups of 8
    const int ty = t >> 4;          // 16 row groups of 8
    const int col = tx * 8;
    const int rbase = ty * 8;

    unsigned long long acc[8][4];

    // ---- GEMM 1: h = relu(tile @ wa + ba) ----
    {
        float4 bv0 = *reinterpret_cast<const float4*>(ba + col);
        float4 bv1 = *reinterpret_cast<const float4*>(ba + col + 4);
        unsigned long long bp[4] = {pack2(bv0.x, bv0.y), pack2(bv0.z, bv0.w),
                                    pack2(bv1.x, bv1.y), pack2(bv1.z, bv1.w)};
#pragma unroll
        for (int i = 0; i < 8; i++)
#pragma unroll
            for (int j = 0; j < 4; j++) acc[i][j] = bp[j];
    }
#pragma unroll 2
    for (int k4 = 0; k4 < DF / 4; k4++) {
        const int k = k4 * 4;
        float a_[8][4];
#pragma unroll
        for (int i = 0; i < 8; i++) {
            float4 f = *reinterpret_cast<const float4*>(&tile[(rbase + i) * TLD + k]);
            a_[i][0] = f.x; a_[i][1] = f.y; a_[i][2] = f.z; a_[i][3] = f.w;
        }
#pragma unroll
        for (int kk = 0; kk < 4; kk++) {
            ulonglong2 q0 = *reinterpret_cast<const ulonglong2*>(&ws_a[(k + kk) * DF + col]);
            ulonglong2 q1 = *reinterpret_cast<const ulonglong2*>(&ws_a[(k + kk) * DF + col + 4]);
#pragma unroll
            for (int i = 0; i < 8; i++) {
                unsigned long long ap = packdup(a_[i][kk]);
                FMA2(acc[i][0], ap, q0.x, acc[i][0]);
                FMA2(acc[i][1], ap, q0.y, acc[i][1]);
                FMA2(acc[i][2], ap, q1.x, acc[i][2]);
                FMA2(acc[i][3], ap, q1.y, acc[i][3]);
            }
        }
    }
    __syncthreads();
#pragma unroll
    for (int i = 0; i < 8; i++) {
        float v[8];
#pragma unroll
        for (int j = 0; j < 4; j++) {
            uint2 u = *reinterpret_cast<uint2*>(&acc[i][j]);
            v[2 * j]     = fmaxf(__uint_as_float(u.x), 0.f);
            v[2 * j + 1] = fmaxf(__uint_as_float(u.y), 0.f);
        }
        *reinterpret_cast<float4*>(&tile[(rbase + i) * TLD + col]) =
            make_float4(v[0], v[1], v[2], v[3]);
        *reinterpret_cast<float4*>(&tile[(rbase + i) * TLD + col + 4]) =
            make_float4(v[4], v[5], v[6], v[7]);
    }
    __syncthreads();

    // ---- GEMM 2: y = relu(h @ wb + bb) ----
    {
        float4 bv0 = *reinterpret_cast<const float4*>(bb + col);
        float4 bv1 = *reinterpret_cast<const float4*>(bb + col + 4);
        unsigned long long bp[4] = {pack2(bv0.x, bv0.y), pack2(bv0.z, bv0.w),
                                    pack2(bv1.x, bv1.y), pack2(bv1.z, bv1.w)};
#pragma unroll
        for (int i = 0; i < 8; i++)
#pragma unroll
            for (int j = 0; j < 4; j++) acc[i][j] = bp[j];
    }
#pragma unroll 2
    for (int k4 = 0; k4 < DF / 4; k4++) {
        const int k = k4 * 4;
        float a_[8][4];
#pragma unroll
        for (int i = 0; i < 8; i++) {
            float4 f = *reinterpret_cast<const float4*>(&tile[(rbase + i) * TLD + k]);
            a_[i][0] = f.x; a_[i][1] = f.y; a_[i][2] = f.z; a_[i][3] = f.w;
        }
#pragma unroll
        for (int kk = 0; kk < 4; kk++) {
            ulonglong2 q0 = *reinterpret_cast<const ulonglong2*>(&ws_b[(k + kk) * DF + col]);
            ulonglong2 q1 = *reinterpret_cast<const ulonglong2*>(&ws_b[(k + kk) * DF + col + 4]);
#pragma unroll
            for (int i = 0; i < 8; i++) {
                unsigned long long ap = packdup(a_[i][kk]);
                FMA2(acc[i][0], ap, q0.x, acc[i][0]);
                FMA2(acc[i][1], ap, q0.y, acc[i][1]);
                FMA2(acc[i][2], ap, q1.x, acc[i][2]);
                FMA2(acc[i][3], ap, q1.y, acc[i][3]);
            }
        }
    }

    if (!do_fc) {
        // Plain layer: write relu(y) to out (h1).
#pragma unroll
        for (int i = 0; i < 8; i++) {
            int gr = row0 + rbase + i;
            if (gr >= NNODES) continue;
            float v[8];
#pragma unroll
            for (int j = 0; j < 4; j++) {
                uint2 u = *reinterpret_cast<uint2*>(&acc[i][j]);
                v[2 * j]     = fmaxf(__uint_as_float(u.x), 0.f);
                v[2 * j + 1] = fmaxf(__uint_as_float(u.y), 0.f);
            }
            *reinterpret_cast<float4*>(out + (size_t)gr * DF + col) =
                make_float4(v[0], v[1], v[2], v[3]);
            *reinterpret_cast<float4*>(out + (size_t)gr * DF + col + 4) =
                make_float4(v[4], v[5], v[6], v[7]);
        }
        return;
    }

    // ---- FC + log_softmax epilogue ----
    __syncthreads();   // all reads of tile (h) complete
#pragma unroll
    for (int i = 0; i < 8; i++) {
        float v[8];
#pragma unroll
        for (int j = 0; j < 4; j++) {
            uint2 u = *reinterpret_cast<uint2*>(&acc[i][j]);
            v[2 * j]     = fmaxf(__uint_as_float(u.x), 0.f);
            v[2 * j + 1] = fmaxf(__uint_as_float(u.y), 0.f);
        }
        *reinterpret_cast<float4*>(&tile[(rbase + i) * TLD + col]) =
            make_float4(v[0], v[1], v[2], v[3]);
        *reinterpret_cast<float4*>(&tile[(rbase + i) * TLD + col + 4]) =
            make_float4(v[4], v[5], v[6], v[7]);
    }
    __syncthreads();

    // Thread t -> row = t>>1, half = t&1 (20 classes each).
    {
        const int r = t >> 1;
        const int half = t & 1;
        const int cb = half * 20;
        float lg[20];
#pragma unroll
        for (int j = 0; j < 20; j++) lg[j] = bsf[cb + j];
#pragma unroll 4
        for (int k = 0; k < DF; k++) {
            float a = tile[r * TLD + k];
            const float* wr = &wsf[k * NCLS + cb];
#pragma unroll
            for (int j = 0; j < 20; j++) lg[j] += a * wr[j];
        }
        float m = -1e30f;
#pragma unroll
        for (int j = 0; j < 20; j++) m = fmaxf(m, lg[j]);
        m = fmaxf(m, __shfl_xor_sync(0xffffffffu, m, 1));
        float s = 0.f;
#pragma unroll
        for (int j = 0; j < 20; j++) s += expf(lg[j] - m);
        s += __shfl_xor_sync(0xffffffffu, s, 1);
        float ls = logf(s);
        int gr = row0 + r;
        if (gr < NNODES) {
            float4 o[5];
#pragma unroll
            for (int q = 0; q < 5; q++)
                o[q] = make_float4(lg[q * 4] - m - ls, lg[q * 4 + 1] - m - ls,
                                   lg[q * 4 + 2] - m - ls, lg[q * 4 + 3] - m - ls);
#pragma unroll
            for (int q = 0; q < 5; q++)
                *reinterpret_cast<float4*>(out + (size_t)gr * NCLS + cb + q * 4) = o[q];
        }
    }
}

// ---------------------------------------------------------------------------
extern "C" void kernel_launch(void* const* d_in, const int* in_sizes, int n_in,
                              void* d_out, int out_size) {
    const float* x        = (const float*)d_in[0];
    const int*   ei_raw   = (const int*)d_in[1];
    const float* w1a      = (const float*)d_in[2];
    const float* b1a      = (const float*)d_in[3];
    const float* w1b      = (const float*)d_in[4];
    const float* b1b      = (const float*)d_in[5];
    const float* w2a      = (const float*)d_in[6];
    const float* b2a      = (const float*)d_in[7];
    const float* w2b      = (const float*)d_in[8];
    const float* b2b      = (const float*)d_in[9];
    const float* wfc      = (const float*)d_in[10];
    const float* bfc      = (const float*)d_in[11];
    float* out            = (float*)d_out;

    float *h1;
    int *csr, *deg, *off, *cur;
    cudaGetSymbolAddress((void**)&h1, g_h1);
    cudaGetSymbolAddress((void**)&csr, g_csr);
    cudaGetSymbolAddress((void**)&deg, g_deg);
    cudaGetSymbolAddress((void**)&off, g_off);
    cudaGetSymbolAddress((void**)&cur, g_cur);

    const size_t smem = (size_t)(2 * DF * DF + TM * TLD + DF * NCLS + NCLS + 8)
                        * sizeof(float);
    cudaFuncSetAttribute(gin_layer_kernel,
                         cudaFuncAttributeMaxDynamicSharedMemorySize, (int)smem);

    const int egrid = (NEDGES + 255) / 256;
    const int ngrid = (NNODES + 255) / 256;
    const int mgrid = (NNODES + TM - 1) / TM;

    // --- CSR build ---
    zero_int_kernel<<<ngrid, 256>>>(deg, NNODES);
    hist_kernel<<<egrid, 256>>>(ei_raw, deg);
    scan_kernel<<<1, SCAN_T>>>(deg, off, cur);
    scatter_kernel<<<egrid, 256>>>(ei_raw, cur, csr);

    // Layer 1: gather(x) + MLP -> h1
    gin_layer_kernel<<<mgrid, 256, smem>>>(x, off, csr, w1a, b1a, w1b, b1b,
                                           nullptr, nullptr, h1);
    // Layer 2: gather(h1) + MLP + FC + log_softmax -> out
    gin_layer_kernel<<<mgrid, 256, smem>>>(h1, off, csr, w2a, b2a, w2b, b2b,
                                           wfc, bfc, out);
}

// round 7
// speedup vs baseline: 1.2697x; 1.0894x over previous
#include <cuda_runtime.h>

#define NNODES 100000
#define NEDGES 1600000
#define DF 128
#define NCLS 40
#define TM 64
#define TLD 132   // padded stride (floats), 16B-aligned rows
#define SCAN_T 1024
#define SCAN_CHUNK ((NNODES + SCAN_T - 1) / SCAN_T)   // 98

// Scratch (allocation-free rule: __device__ globals)
__device__ float g_pre[NNODES * DF];
__device__ float g_h1[NNODES * DF];
__device__ int   g_csr[NEDGES];
__device__ int   g_deg[NNODES];
__device__ int   g_off[NNODES + 1];
__device__ int   g_cur[NNODES];

// ---- packed f32x2 helpers ---------------------------------------------------
__device__ __forceinline__ unsigned long long pack2(float x, float y) {
    unsigned long long r;
    asm("mov.b64 %0, {%1,%2};" : "=l"(r)
        : "r"(__float_as_uint(x)), "r"(__float_as_uint(y)));
    return r;
}
#define FMA2(d, a, b, c) \
    asm("fma.rn.f32x2 %0, %1, %2, %3;" : "=l"(d) : "l"(a), "l"(b), "l"(c))

__device__ __forceinline__ bool edges_are_i64(const int* raw) {
    return (raw[1] | raw[3] | raw[5] | raw[7] |
            raw[9] | raw[11] | raw[13] | raw[15]) == 0;
}

// ---------------------------------------------------------------------------
__global__ void zero_int_kernel(int* __restrict__ p, int n) {
    int i = blockIdx.x * blockDim.x + threadIdx.x;
    if (i < n) p[i] = 0;
}

__global__ void hist_kernel(const int* __restrict__ raw, int* __restrict__ deg) {
    bool is64 = edges_are_i64(raw);
    int i = blockIdx.x * blockDim.x + threadIdx.x;
    if (i >= NEDGES) return;
    int d = is64 ? raw[2 * NEDGES + 2 * i] : raw[NEDGES + i];
    atomicAdd(deg + d, 1);
}

__global__ __launch_bounds__(SCAN_T, 1)
void scan_kernel(const int* __restrict__ deg, int* __restrict__ off,
                 int* __restrict__ cur) {
    __shared__ int s[SCAN_T];
    int t = threadIdx.x;
    int base = t * SCAN_CHUNK;
    int sum = 0;
    for (int i = 0; i < SCAN_CHUNK; i++) {
        int idx = base + i;
        if (idx < NNODES) sum += deg[idx];
    }
    s[t] = sum;
    __syncthreads();
    for (int ofs = 1; ofs < SCAN_T; ofs <<= 1) {
        int v = (t >= ofs) ? s[t - ofs] : 0;
        __syncthreads();
        s[t] += v;
        __syncthreads();
    }
    int run = (t == 0) ? 0 : s[t - 1];
    for (int i = 0; i < SCAN_CHUNK; i++) {
        int idx = base + i;
        if (idx < NNODES) {
            off[idx] = run;
            cur[idx] = run;
            run += deg[idx];
        }
    }
    if (t == 0) off[NNODES] = s[SCAN_T - 1];
}

__global__ void scatter_kernel(const int* __restrict__ raw,
                               int* __restrict__ cur,
                               int* __restrict__ csr) {
    bool is64 = edges_are_i64(raw);
    int i = blockIdx.x * blockDim.x + threadIdx.x;
    if (i >= NEDGES) return;
    int s, d;
    if (is64) { s = raw[2 * i]; d = raw[2 * NEDGES + 2 * i]; }
    else      { s = raw[i];     d = raw[NEDGES + i]; }
    int pos = atomicAdd(cur + d, 1);
    csr[pos] = s;
}

// ---------------------------------------------------------------------------
// Gather aggregation (high occupancy): pre[node] = xin[node] + sum feat[nbr].
__global__ void agg_kernel(const float* __restrict__ feat,
                           const float* __restrict__ xin,
                           const int* __restrict__ off,
                           const int* __restrict__ csr,
                           float* __restrict__ pre) {
    int node = (blockIdx.x * blockDim.x + threadIdx.x) >> 5;
    int lane = threadIdx.x & 31;
    if (node >= NNODES) return;
    int e0 = off[node], e1 = off[node + 1];
    float4 acc = reinterpret_cast<const float4*>(xin + (size_t)node * DF)[lane];
    int e = e0;
#pragma unroll 1
    for (; e + 8 <= e1; e += 8) {
        int n[8];
#pragma unroll
        for (int j = 0; j < 8; j++) n[j] = __ldg(csr + e + j);
        float4 v[8];
#pragma unroll
        for (int j = 0; j < 8; j++)
            v[j] = *reinterpret_cast<const float4*>(feat + (size_t)n[j] * DF + lane * 4);
#pragma unroll
        for (int j = 0; j < 8; j++) {
            acc.x += v[j].x; acc.y += v[j].y; acc.z += v[j].z; acc.w += v[j].w;
        }
    }
    for (; e < e1; e++) {
        int n0 = __ldg(csr + e);
        float4 v0 = *reinterpret_cast<const float4*>(feat + (size_t)n0 * DF + lane * 4);
        acc.x += v0.x; acc.y += v0.y; acc.z += v0.z; acc.w += v0.w;
    }
    *reinterpret_cast<float4*>(pre + (size_t)node * DF + lane * 4) = acc;
}

// ---------------------------------------------------------------------------
// Fused GIN MLP, k-paired f32x2 FMA (no duplication MOVs), 64-row tile,
// 256 threads. Weights stored TRANSPOSED in smem: wt[n*TLD + k].
// acc lanes: lo = even-k partials, hi = odd-k partials; reduced at epilogue.
// Optional FC(128->40) + log_softmax epilogue when wfc != nullptr.
__global__ __launch_bounds__(256, 1)
void mlp_kernel(const float* __restrict__ pre,
                const float* __restrict__ wa, const float* __restrict__ ba,
                const float* __restrict__ wb, const float* __restrict__ bb,
                const float* __restrict__ wfc, const float* __restrict__ bfc,
                float* __restrict__ out) {
    extern __shared__ float sm[];
    float* wt_a = sm;                         // 128*TLD
    float* wt_b = sm + DF * TLD;              // 128*TLD
    float* tile = sm + 2 * DF * TLD;          // TM*TLD
    float* wsf  = tile + TM * TLD;            // DF*NCLS (fc only)
    float* bsf  = wsf + DF * NCLS;            // NCLS

    const int t = threadIdx.x;
    const int row0 = blockIdx.x * TM;
    const bool do_fc = (wfc != nullptr);

    // Load weights transposed: wt[n][k] = w[k][n]
    for (int i = t; i < DF * DF; i += 256) {
        int k = i >> 7, n = i & 127;
        wt_a[n * TLD + k] = wa[i];
        wt_b[n * TLD + k] = wb[i];
    }
    if (do_fc) {
        for (int i = t; i < DF * NCLS; i += 256) wsf[i] = wfc[i];
        if (t < NCLS) bsf[t] = bfc[t];
    }

    // Load input tile (64 rows x 128 cols)
    {
        int c4 = t & 31;
        int rr = t >> 5;   // 0..7
#pragma unroll
        for (int i = 0; i < TM / 8; i++) {
            int r = rr + i * 8;
            int gr = row0 + r;
            float4 v = make_float4(0.f, 0.f, 0.f, 0.f);
            if (gr < NNODES)
                v = reinterpret_cast<const float4*>(pre + (size_t)gr * DF)[c4];
            *reinterpret_cast<float4*>(&tile[r * TLD + c4 * 4]) = v;
        }
    }
    __syncthreads();

    const int tx = t & 15;          // col base: cols tx + 16j, j=0..7
    const int ty = t >> 4;          // row group: rows ty*4 .. ty*4+3
    const int rbase = ty * 4;

    unsigned long long acc[4][8];

#define GEMM_KPAIR(WT, BIAS)                                                  \
    {                                                                         \
        _Pragma("unroll")                                                     \
        for (int j = 0; j < 8; j++) {                                         \
            unsigned long long bj = pack2(BIAS[tx + 16 * j], 0.f);            \
            _Pragma("unroll")                                                 \
            for (int i = 0; i < 4; i++) acc[i][j] = bj;                       \
        }                                                                     \
        _Pragma("unroll 2")                                                   \
        for (int k4 = 0; k4 < DF / 4; k4++) {                                 \
            const int k = k4 * 4;                                             \
            ulonglong2 ap[4];                                                 \
            _Pragma("unroll")                                                 \
            for (int i = 0; i < 4; i++)                                       \
                ap[i] = *reinterpret_cast<const ulonglong2*>(                 \
                    &tile[(rbase + i) * TLD + k]);                            \
            _Pragma("unroll")                                                 \
            for (int j = 0; j < 8; j++) {                                     \
                ulonglong2 bp = *reinterpret_cast<const ulonglong2*>(         \
                    &WT[(tx + 16 * j) * TLD + k]);                            \
                _Pragma("unroll")                                             \
                for (int i = 0; i < 4; i++) {                                 \
                    FMA2(acc[i][j], ap[i].x, bp.x, acc[i][j]);                \
                    FMA2(acc[i][j], ap[i].y, bp.y, acc[i][j]);                \
                }                                                             \
            }                                                                 \
        }                                                                     \
    }

    // ---- GEMM 1: h = relu(tile @ wa + ba) ----
    GEMM_KPAIR(wt_a, ba)
    __syncthreads();   // all tile reads done
#pragma unroll
    for (int i = 0; i < 4; i++)
#pragma unroll
        for (int j = 0; j < 8; j++) {
            uint2 u = *reinterpret_cast<uint2*>(&acc[i][j]);
            float v = fmaxf(__uint_as_float(u.x) + __uint_as_float(u.y), 0.f);
            tile[(rbase + i) * TLD + tx + 16 * j] = v;
        }
    __syncthreads();

    // ---- GEMM 2: y = relu(h @ wb + bb) ----
    GEMM_KPAIR(wt_b, bb)

    if (!do_fc) {
#pragma unroll
        for (int i = 0; i < 4; i++) {
            int gr = row0 + rbase + i;
            if (gr >= NNODES) continue;
#pragma unroll
            for (int j = 0; j < 8; j++) {
                uint2 u = *reinterpret_cast<uint2*>(&acc[i][j]);
                float v = fmaxf(__uint_as_float(u.x) + __uint_as_float(u.y), 0.f);
                out[(size_t)gr * DF + tx + 16 * j] = v;
            }
        }
        return;
    }

    // ---- FC + log_softmax epilogue ----
    __syncthreads();   // all tile (h) reads done
#pragma unroll
    for (int i = 0; i < 4; i++)
#pragma unroll
        for (int j = 0; j < 8; j++) {
            uint2 u = *reinterpret_cast<uint2*>(&acc[i][j]);
            float v = fmaxf(__uint_as_float(u.x) + __uint_as_float(u.y), 0.f);
            tile[(rbase + i) * TLD + tx + 16 * j] = v;
        }
    __syncthreads();

    // Thread t -> row r = t>>2, quarter q = t&3 (10 classes each).
    {
        const int r = t >> 2;
        const int q = t & 3;
        const int cb = q * 10;
        float lg[10];
#pragma unroll
        for (int j = 0; j < 10; j++) lg[j] = bsf[cb + j];
#pragma unroll 4
        for (int k = 0; k < DF; k++) {
            float a = tile[r * TLD + k];
            const float* wr = &wsf[k * NCLS + cb];
#pragma unroll
            for (int j = 0; j < 10; j++) lg[j] += a * wr[j];
        }
        float m = -1e30f;
#pragma unroll
        for (int j = 0; j < 10; j++) m = fmaxf(m, lg[j]);
        m = fmaxf(m, __shfl_xor_sync(0xffffffffu, m, 1));
        m = fmaxf(m, __shfl_xor_sync(0xffffffffu, m, 2));
        float s = 0.f;
#pragma unroll
        for (int j = 0; j < 10; j++) s += expf(lg[j] - m);
        s += __shfl_xor_sync(0xffffffffu, s, 1);
        s += __shfl_xor_sync(0xffffffffu, s, 2);
        float ls = logf(s) + m;
        int gr = row0 + r;
        if (gr < NNODES) {
#pragma unroll
            for (int j = 0; j < 10; j++)
                out[(size_t)gr * NCLS + cb + j] = lg[j] - ls;
        }
    }
}

// ---------------------------------------------------------------------------
extern "C" void kernel_launch(void* const* d_in, const int* in_sizes, int n_in,
                              void* d_out, int out_size) {
    const float* x        = (const float*)d_in[0];
    const int*   ei_raw   = (const int*)d_in[1];
    const float* w1a      = (const float*)d_in[2];
    const float* b1a      = (const float*)d_in[3];
    const float* w1b      = (const float*)d_in[4];
    const float* b1b      = (const float*)d_in[5];
    const float* w2a      = (const float*)d_in[6];
    const float* b2a      = (const float*)d_in[7];
    const float* w2b      = (const float*)d_in[8];
    const float* b2b      = (const float*)d_in[9];
    const float* wfc      = (const float*)d_in[10];
    const float* bfc      = (const float*)d_in[11];
    float* out            = (float*)d_out;

    float *pre, *h1;
    int *csr, *deg, *off, *cur;
    cudaGetSymbolAddress((void**)&pre, g_pre);
    cudaGetSymbolAddress((void**)&h1, g_h1);
    cudaGetSymbolAddress((void**)&csr, g_csr);
    cudaGetSymbolAddress((void**)&deg, g_deg);
    cudaGetSymbolAddress((void**)&off, g_off);
    cudaGetSymbolAddress((void**)&cur, g_cur);

    const size_t smem = (size_t)(2 * DF * TLD + TM * TLD + DF * NCLS + NCLS + 8)
                        * sizeof(float);
    cudaFuncSetAttribute(mlp_kernel,
                         cudaFuncAttributeMaxDynamicSharedMemorySize, (int)smem);

    const int egrid = (NEDGES + 255) / 256;
    const int ngrid = (NNODES + 255) / 256;
    const int agrid = (int)(((long long)NNODES * 32 + 255) / 256);
    const int mgrid = (NNODES + TM - 1) / TM;

    // --- CSR build ---
    zero_int_kernel<<<ngrid, 256>>>(deg, NNODES);
    hist_kernel<<<egrid, 256>>>(ei_raw, deg);
    scan_kernel<<<1, SCAN_T>>>(deg, off, cur);
    scatter_kernel<<<egrid, 256>>>(ei_raw, cur, csr);

    // Layer 1
    agg_kernel<<<agrid, 256>>>(x, x, off, csr, pre);
    mlp_kernel<<<mgrid, 256, smem>>>(pre, w1a, b1a, w1b, b1b,
                                     nullptr, nullptr, h1);
    // Layer 2 (+ fused FC/log_softmax)
    agg_kernel<<<agrid, 256>>>(h1, h1, off, csr, pre);
    mlp_kernel<<<mgrid, 256, smem>>>(pre, w2a, b2a, w2b, b2b,
                                     wfc, bfc, out);
}

// round 8
// speedup vs baseline: 1.4935x; 1.1763x over previous
#include <cuda_runtime.h>

#define NNODES 100000
#define NEDGES 1600000
#define DF 128
#define NCLS 40
#define TM 128
#define TLD 132   // padded tile stride (floats)
#define SCAN_T 1024
#define SCAN_CHUNK ((NNODES + SCAN_T - 1) / SCAN_T)   // 98

// Scratch (allocation-free rule: __device__ globals)
__device__ float g_pre[NNODES * DF];
__device__ float g_h1[NNODES * DF];
__device__ int   g_csr[NEDGES];
__device__ int   g_deg[NNODES];
__device__ int   g_off[NNODES + 1];
__device__ int   g_cur[NNODES];

// ---- packed f32x2 helpers ---------------------------------------------------
__device__ __forceinline__ unsigned long long pack2(float x, float y) {
    unsigned long long r;
    asm("mov.b64 %0, {%1,%2};" : "=l"(r)
        : "r"(__float_as_uint(x)), "r"(__float_as_uint(y)));
    return r;
}
__device__ __forceinline__ unsigned long long packdup(float x) {
    unsigned long long r;
    asm("mov.b64 %0, {%1,%1};" : "=l"(r) : "r"(__float_as_uint(x)));
    return r;
}
#define FMA2(d, a, b, c) \
    asm("fma.rn.f32x2 %0, %1, %2, %3;" : "=l"(d) : "l"(a), "l"(b), "l"(c))

__device__ __forceinline__ bool edges_are_i64(const int* raw) {
    return (raw[1] | raw[3] | raw[5] | raw[7] |
            raw[9] | raw[11] | raw[13] | raw[15]) == 0;
}

// ---------------------------------------------------------------------------
__global__ void zero_int_kernel(int* __restrict__ p, int n) {
    int i = blockIdx.x * blockDim.x + threadIdx.x;
    if (i < n) p[i] = 0;
}

__global__ void hist_kernel(const int* __restrict__ raw, int* __restrict__ deg) {
    bool is64 = edges_are_i64(raw);
    int i = blockIdx.x * blockDim.x + threadIdx.x;
    if (i >= NEDGES) return;
    int d = is64 ? raw[2 * NEDGES + 2 * i] : raw[NEDGES + i];
    atomicAdd(deg + d, 1);
}

__global__ __launch_bounds__(SCAN_T, 1)
void scan_kernel(const int* __restrict__ deg, int* __restrict__ off,
                 int* __restrict__ cur) {
    __shared__ int s[SCAN_T];
    int t = threadIdx.x;
    int base = t * SCAN_CHUNK;
    int sum = 0;
    for (int i = 0; i < SCAN_CHUNK; i++) {
        int idx = base + i;
        if (idx < NNODES) sum += deg[idx];
    }
    s[t] = sum;
    __syncthreads();
    for (int ofs = 1; ofs < SCAN_T; ofs <<= 1) {
        int v = (t >= ofs) ? s[t - ofs] : 0;
        __syncthreads();
        s[t] += v;
        __syncthreads();
    }
    int run = (t == 0) ? 0 : s[t - 1];
    for (int i = 0; i < SCAN_CHUNK; i++) {
        int idx = base + i;
        if (idx < NNODES) {
            off[idx] = run;
            cur[idx] = run;
            run += deg[idx];
        }
    }
    if (t == 0) off[NNODES] = s[SCAN_T - 1];
}

__global__ void scatter_kernel(const int* __restrict__ raw,
                               int* __restrict__ cur,
                               int* __restrict__ csr) {
    bool is64 = edges_are_i64(raw);
    int i = blockIdx.x * blockDim.x + threadIdx.x;
    if (i >= NEDGES) return;
    int s, d;
    if (is64) { s = raw[2 * i]; d = raw[2 * NEDGES + 2 * i]; }
    else      { s = raw[i];     d = raw[NEDGES + i]; }
    int pos = atomicAdd(cur + d, 1);
    csr[pos] = s;
}

// ---------------------------------------------------------------------------
// Gather aggregation (high occupancy): pre[node] = xin[node] + sum feat[nbr].
__global__ void agg_kernel(const float* __restrict__ feat,
                           const float* __restrict__ xin,
                           const int* __restrict__ off,
                           const int* __restrict__ csr,
                           float* __restrict__ pre) {
    int node = (blockIdx.x * blockDim.x + threadIdx.x) >> 5;
    int lane = threadIdx.x & 31;
    if (node >= NNODES) return;
    int e0 = off[node], e1 = off[node + 1];
    float4 acc = reinterpret_cast<const float4*>(xin + (size_t)node * DF)[lane];
    int e = e0;
#pragma unroll 1
    for (; e + 8 <= e1; e += 8) {
        int n[8];
#pragma unroll
        for (int j = 0; j < 8; j++) n[j] = __ldg(csr + e + j);
        float4 v[8];
#pragma unroll
        for (int j = 0; j < 8; j++)
            v[j] = *reinterpret_cast<const float4*>(feat + (size_t)n[j] * DF + lane * 4);
#pragma unroll
        for (int j = 0; j < 8; j++) {
            acc.x += v[j].x; acc.y += v[j].y; acc.z += v[j].z; acc.w += v[j].w;
        }
    }
    for (; e < e1; e++) {
        int n0 = __ldg(csr + e);
        float4 v0 = *reinterpret_cast<const float4*>(feat + (size_t)n0 * DF + lane * 4);
        acc.x += v0.x; acc.y += v0.y; acc.z += v0.z; acc.w += v0.w;
    }
    *reinterpret_cast<float4*>(pre + (size_t)node * DF + lane * 4) = acc;
}

// ---------------------------------------------------------------------------
// Fused GIN MLP (round-4 core): packed f32x2 FMA, 128-row tile, 256 threads,
// 8 rows x 8 cols per thread. Optional FC(128->40)+log_softmax epilogue.
__global__ __launch_bounds__(256, 1)
void mlp_kernel(const float* __restrict__ pre,
                const float* __restrict__ wa, const float* __restrict__ ba,
                const float* __restrict__ wb, const float* __restrict__ bb,
                const float* __restrict__ wfc, const float* __restrict__ bfc,
                float* __restrict__ out) {
    extern __shared__ float sm[];
    float* ws_a = sm;                 // 128*128
    float* ws_b = sm + DF * DF;       // 128*128
    float* tile = sm + 2 * DF * DF;   // TM*TLD (input, then h)
    float* wsf  = tile + TM * TLD;    // DF*NCLS (fc only)
    float* bsf  = wsf + DF * NCLS;    // NCLS

    const int t = threadIdx.x;
    const int row0 = blockIdx.x * TM;
    const bool do_fc = (wfc != nullptr);

    // Load both weight matrices (k-major: w[k*128 + n])
    {
        const float4* wa4 = reinterpret_cast<const float4*>(wa);
        const float4* wb4 = reinterpret_cast<const float4*>(wb);
        float4* wsa4 = reinterpret_cast<float4*>(ws_a);
        float4* wsb4 = reinterpret_cast<float4*>(ws_b);
#pragma unroll
        for (int i = 0; i < (DF * DF / 4) / 256; i++) {
            wsa4[t + i * 256] = wa4[t + i * 256];
            wsb4[t + i * 256] = wb4[t + i * 256];
        }
        if (do_fc) {
            for (int i = t; i < DF * NCLS; i += 256) wsf[i] = wfc[i];
            if (t < NCLS) bsf[t] = bfc[t];
        }
    }

    // Load input tile (128 rows x 128 cols)
    {
        int c4 = t & 31;
        int rr = t >> 5;
#pragma unroll
        for (int i = 0; i < TM / 8; i++) {
            int r = rr + i * 8;
            int gr = row0 + r;
            float4 v = make_float4(0.f, 0.f, 0.f, 0.f);
            if (gr < NNODES)
                v = reinterpret_cast<const float4*>(pre + (size_t)gr * DF)[c4];
            *reinterpret_cast<float4*>(&tile[r * TLD + c4 * 4]) = v;
        }
    }
    __syncthreads();

    const int tx = t & 15;          // 16 column groups of 8
    const int ty = t >> 4;          // 16 row groups of 8
    const int col = tx * 8;
    const int rbase = ty * 8;

    unsigned long long acc[8][4];

    // ---- GEMM 1: h = relu(tile @ wa + ba) ----
    {
        float4 bv0 = *reinterpret_cast<const float4*>(ba + col);
        float4 bv1 = *reinterpret_cast<const float4*>(ba + col + 4);
        unsigned long long bp[4] = {pack2(bv0.x, bv0.y), pack2(bv0.z, bv0.w),
                                    pack2(bv1.x, bv1.y), pack2(bv1.z, bv1.w)};
#pragma unroll
        for (int i = 0; i < 8; i++)
#pragma unroll
            for (int j = 0; j < 4; j++) acc[i][j] = bp[j];
    }
#pragma unroll 2
    for (int k4 = 0; k4 < DF / 4; k4++) {
        const int k = k4 * 4;
        float a_[8][4];
#pragma unroll
        for (int i = 0; i < 8; i++) {
            float4 f = *reinterpret_cast<const float4*>(&tile[(rbase + i) * TLD + k]);
            a_[i][0] = f.x; a_[i][1] = f.y; a_[i][2] = f.z; a_[i][3] = f.w;
        }
#pragma unroll
        for (int kk = 0; kk < 4; kk++) {
            ulonglong2 q0 = *reinterpret_cast<const ulonglong2*>(&ws_a[(k + kk) * DF + col]);
            ulonglong2 q1 = *reinterpret_cast<const ulonglong2*>(&ws_a[(k + kk) * DF + col + 4]);
#pragma unroll
            for (int i = 0; i < 8; i++) {
                unsigned long long ap = packdup(a_[i][kk]);
                FMA2(acc[i][0], ap, q0.x, acc[i][0]);
                FMA2(acc[i][1], ap, q0.y, acc[i][1]);
                FMA2(acc[i][2], ap, q1.x, acc[i][2]);
                FMA2(acc[i][3], ap, q1.y, acc[i][3]);
            }
        }
    }
    __syncthreads();   // all reads of tile complete
#pragma unroll
    for (int i = 0; i < 8; i++) {
        float v[8];
#pragma unroll
        for (int j = 0; j < 4; j++) {
            uint2 u = *reinterpret_cast<uint2*>(&acc[i][j]);
            v[2 * j]     = fmaxf(__uint_as_float(u.x), 0.f);
            v[2 * j + 1] = fmaxf(__uint_as_float(u.y), 0.f);
        }
        *reinterpret_cast<float4*>(&tile[(rbase + i) * TLD + col]) =
            make_float4(v[0], v[1], v[2], v[3]);
        *reinterpret_cast<float4*>(&tile[(rbase + i) * TLD + col + 4]) =
            make_float4(v[4], v[5], v[6], v[7]);
    }
    __syncthreads();

    // ---- GEMM 2: y = relu(h @ wb + bb) ----
    {
        float4 bv0 = *reinterpret_cast<const float4*>(bb + col);
        float4 bv1 = *reinterpret_cast<const float4*>(bb + col + 4);
        unsigned long long bp[4] = {pack2(bv0.x, bv0.y), pack2(bv0.z, bv0.w),
                                    pack2(bv1.x, bv1.y), pack2(bv1.z, bv1.w)};
#pragma unroll
        for (int i = 0; i < 8; i++)
#pragma unroll
            for (int j = 0; j < 4; j++) acc[i][j] = bp[j];
    }
#pragma unroll 2
    for (int k4 = 0; k4 < DF / 4; k4++) {
        const int k = k4 * 4;
        float a_[8][4];
#pragma unroll
        for (int i = 0; i < 8; i++) {
            float4 f = *reinterpret_cast<const float4*>(&tile[(rbase + i) * TLD + k]);
            a_[i][0] = f.x; a_[i][1] = f.y; a_[i][2] = f.z; a_[i][3] = f.w;
        }
#pragma unroll
        for (int kk = 0; kk < 4; kk++) {
            ulonglong2 q0 = *reinterpret_cast<const ulonglong2*>(&ws_b[(k + kk) * DF + col]);
            ulonglong2 q1 = *reinterpret_cast<const ulonglong2*>(&ws_b[(k + kk) * DF + col + 4]);
#pragma unroll
            for (int i = 0; i < 8; i++) {
                unsigned long long ap = packdup(a_[i][kk]);
                FMA2(acc[i][0], ap, q0.x, acc[i][0]);
                FMA2(acc[i][1], ap, q0.y, acc[i][1]);
                FMA2(acc[i][2], ap, q1.x, acc[i][2]);
                FMA2(acc[i][3], ap, q1.y, acc[i][3]);
            }
        }
    }

    if (!do_fc) {
        // Plain layer: write relu(y) to out (h1).
#pragma unroll
        for (int i = 0; i < 8; i++) {
            int gr = row0 + rbase + i;
            if (gr >= NNODES) continue;
            float v[8];
#pragma unroll
            for (int j = 0; j < 4; j++) {
                uint2 u = *reinterpret_cast<uint2*>(&acc[i][j]);
                v[2 * j]     = fmaxf(__uint_as_float(u.x), 0.f);
                v[2 * j + 1] = fmaxf(__uint_as_float(u.y), 0.f);
            }
            *reinterpret_cast<float4*>(out + (size_t)gr * DF + col) =
                make_float4(v[0], v[1], v[2], v[3]);
            *reinterpret_cast<float4*>(out + (size_t)gr * DF + col + 4) =
                make_float4(v[4], v[5], v[6], v[7]);
        }
        return;
    }

    // ---- FC + log_softmax epilogue ----
    __syncthreads();   // all reads of tile (h) complete
#pragma unroll
    for (int i = 0; i < 8; i++) {
        float v[8];
#pragma unroll
        for (int j = 0; j < 4; j++) {
            uint2 u = *reinterpret_cast<uint2*>(&acc[i][j]);
            v[2 * j]     = fmaxf(__uint_as_float(u.x), 0.f);
            v[2 * j + 1] = fmaxf(__uint_as_float(u.y), 0.f);
        }
        *reinterpret_cast<float4*>(&tile[(rbase + i) * TLD + col]) =
            make_float4(v[0], v[1], v[2], v[3]);
        *reinterpret_cast<float4*>(&tile[(rbase + i) * TLD + col + 4]) =
            make_float4(v[4], v[5], v[6], v[7]);
    }
    __syncthreads();

    // Thread t -> row r = t>>1, half = t&1 (20 classes each).
    {
        const int r = t >> 1;
        const int half = t & 1;
        const int cb = half * 20;
        float lg[20];
#pragma unroll
        for (int j = 0; j < 20; j++) lg[j] = bsf[cb + j];
#pragma unroll 4
        for (int k = 0; k < DF; k++) {
            float a = tile[r * TLD + k];
            const float* wr = &wsf[k * NCLS + cb];
#pragma unroll
            for (int j = 0; j < 20; j++) lg[j] += a * wr[j];
        }
        float m = -1e30f;
#pragma unroll
        for (int j = 0; j < 20; j++) m = fmaxf(m, lg[j]);
        m = fmaxf(m, __shfl_xor_sync(0xffffffffu, m, 1));
        float s = 0.f;
#pragma unroll
        for (int j = 0; j < 20; j++) s += expf(lg[j] - m);
        s += __shfl_xor_sync(0xffffffffu, s, 1);
        float ls = logf(s) + m;
        int gr = row0 + r;
        if (gr < NNODES) {
            float4 o[5];
#pragma unroll
            for (int q = 0; q < 5; q++)
                o[q] = make_float4(lg[q * 4] - ls, lg[q * 4 + 1] - ls,
                                   lg[q * 4 + 2] - ls, lg[q * 4 + 3] - ls);
#pragma unroll
            for (int q = 0; q < 5; q++)
                *reinterpret_cast<float4*>(out + (size_t)gr * NCLS + cb + q * 4) = o[q];
        }
    }
}

// ---------------------------------------------------------------------------
extern "C" void kernel_launch(void* const* d_in, const int* in_sizes, int n_in,
                              void* d_out, int out_size) {
    const float* x        = (const float*)d_in[0];
    const int*   ei_raw   = (const int*)d_in[1];
    const float* w1a      = (const float*)d_in[2];
    const float* b1a      = (const float*)d_in[3];
    const float* w1b      = (const float*)d_in[4];
    const float* b1b      = (const float*)d_in[5];
    const float* w2a      = (const float*)d_in[6];
    const float* b2a      = (const float*)d_in[7];
    const float* w2b      = (const float*)d_in[8];
    const float* b2b      = (const float*)d_in[9];
    const float* wfc      = (const float*)d_in[10];
    const float* bfc      = (const float*)d_in[11];
    float* out            = (float*)d_out;

    float *pre, *h1;
    int *csr, *deg, *off, *cur;
    cudaGetSymbolAddress((void**)&pre, g_pre);
    cudaGetSymbolAddress((void**)&h1, g_h1);
    cudaGetSymbolAddress((void**)&csr, g_csr);
    cudaGetSymbolAddress((void**)&deg, g_deg);
    cudaGetSymbolAddress((void**)&off, g_off);
    cudaGetSymbolAddress((void**)&cur, g_cur);

    const size_t smem = (size_t)(2 * DF * DF + TM * TLD + DF * NCLS + NCLS + 8)
                        * sizeof(float);
    cudaFuncSetAttribute(mlp_kernel,
                         cudaFuncAttributeMaxDynamicSharedMemorySize, (int)smem);

    const int egrid = (NEDGES + 255) / 256;
    const int ngrid = (NNODES + 255) / 256;
    const int agrid = (int)(((long long)NNODES * 32 + 255) / 256);
    const int mgrid = (NNODES + TM - 1) / TM;

    // --- CSR build ---
    zero_int_kernel<<<ngrid, 256>>>(deg, NNODES);
    hist_kernel<<<egrid, 256>>>(ei_raw, deg);
    scan_kernel<<<1, SCAN_T>>>(deg, off, cur);
    scatter_kernel<<<egrid, 256>>>(ei_raw, cur, csr);

    // Layer 1
    agg_kernel<<<agrid, 256>>>(x, x, off, csr, pre);
    mlp_kernel<<<mgrid, 256, smem>>>(pre, w1a, b1a, w1b, b1b,
                                     nullptr, nullptr, h1);
    // Layer 2 (+ fused FC/log_softmax)
    agg_kernel<<<agrid, 256>>>(h1, h1, off, csr, pre);
    mlp_kernel<<<mgrid, 256, smem>>>(pre, w2a, b2a, w2b, b2b,
                                     wfc, bfc, out);
}